// round 13
// baseline (speedup 1.0000x reference)
#include <cuda_runtime.h>
#include <cuda_fp16.h>
#include <cuda_bf16.h>

#define N_NODES  100000
#define N_EDGES  1600000
#define N_GRAPHS 64
#define HID      64
#define LN_EPS   1e-5f
#define FULL     0xffffffffu
#define EDGE_BLOCKS 1184
#define PRE_BLOCKS  1184
#define NODE_CHUNK  8
#define NODE_WARPS  ((N_NODES + NODE_CHUNK - 1) / NODE_CHUNK)   // 12500
#define NODE_BLOCKS ((NODE_WARPS + 7) / 8)                      // 1563

// -------- persistent device scratch (R7 layout — proven fastest) --------
__device__ uint4  g_xl16[N_NODES * 8];    // att ⊙ (x@W_l), fp16, 8 ch per uint4
__device__ uint4  g_xr16[N_NODES * 8];    // att ⊙ (x@W_r + b_l + b_r), fp16
__device__ float4 g_xw[N_NODES];          // exp(0.6*adl[n]) * x[n]
__device__ float  g_w [N_NODES];          // exp(0.6*adl[n])
__device__ float4 g_acc[N_NODES];         // sum_e t * xw[src]
__device__ float  g_den[N_NODES];         // sum_e ex
__device__ float4 g_wal;                  // W_l^T att
__device__ float  g_sW, g_sB;
__device__ double g_S[N_GRAPHS];
__device__ int    g_cnt[N_GRAPHS];
__device__ double g_sum, g_sq;

// -------- kernel 1: tiny constants (one warp) --------
__global__ void k_const(const float* __restrict__ W_l, const float* __restrict__ att,
                        const float* __restrict__ ln_w, const float* __restrict__ ln_b,
                        const float* __restrict__ lin_w, const float* __restrict__ lin_b) {
    int c = threadIdx.x;
    float a0 = att[c], a1 = att[c + 32];
    float p0 = W_l[0*64+c]*a0 + W_l[0*64+c+32]*a1;
    float p1 = W_l[1*64+c]*a0 + W_l[1*64+c+32]*a1;
    float p2 = W_l[2*64+c]*a0 + W_l[2*64+c+32]*a1;
    float p3 = W_l[3*64+c]*a0 + W_l[3*64+c+32]*a1;
    float sw = ln_w[c]*lin_w[c] + ln_w[c+32]*lin_w[c+32];
    float sb = ln_b[c]*lin_w[c] + ln_b[c+32]*lin_w[c+32];
    #pragma unroll
    for (int off = 16; off > 0; off >>= 1) {
        p0 += __shfl_xor_sync(FULL, p0, off);
        p1 += __shfl_xor_sync(FULL, p1, off);
        p2 += __shfl_xor_sync(FULL, p2, off);
        p3 += __shfl_xor_sync(FULL, p3, off);
        sw += __shfl_xor_sync(FULL, sw, off);
        sb += __shfl_xor_sync(FULL, sb, off);
    }
    if (c == 0) {
        g_wal = make_float4(p0, p1, p2, p3);
        g_sW = sw;
        g_sB = sb + lin_b[0];
        g_sum = 0.0;
        g_sq  = 0.0;
    }
    if (c < N_GRAPHS) { g_S[c] = 0.0; g_cnt[c] = 0; }
    if (c + 32 < N_GRAPHS) { g_S[c + 32] = 0.0; g_cnt[c + 32] = 0; }
}

// -------- kernel 2: node projections -> fp16 + src weights + acc clear --------
// grid-stride over node pairs; warp = 2 nodes/iter; 16 lanes per node
__global__ void __launch_bounds__(256)
k_prehalf(const float* __restrict__ x,
          const float* __restrict__ W_l, const float* __restrict__ W_r,
          const float* __restrict__ att,
          const float* __restrict__ b_l, const float* __restrict__ b_r) {
    int tid  = blockIdx.x * blockDim.x + threadIdx.x;
    int lane = threadIdx.x & 31;
    int half = lane >> 4;
    int j    = lane & 15;

    const float4* x4  = (const float4*)x;
    const float4* wl4 = (const float4*)W_l;
    const float4* wr4 = (const float4*)W_r;
    float4 wl0 = wl4[j], wl1 = wl4[16 + j], wl2 = wl4[32 + j], wl3 = wl4[48 + j];
    float4 wr0 = wr4[j], wr1 = wr4[16 + j], wr2 = wr4[32 + j], wr3 = wr4[48 + j];
    float4 av  = ((const float4*)att)[j];
    float4 bl4 = ((const float4*)b_l)[j];
    float4 br4 = ((const float4*)b_r)[j];

    int warpId = tid >> 5;
    const int NW = (PRE_BLOCKS * 256) >> 5;
    uint2* xl2 = (uint2*)g_xl16;
    uint2* xr2 = (uint2*)g_xr16;

    for (int task = warpId; task < N_NODES / 2; task += NW) {
        int n = task * 2 + half;

        float4 xn = x4[n];
        float lx = xn.x*wl0.x + xn.y*wl1.x + xn.z*wl2.x + xn.w*wl3.x;
        float ly = xn.x*wl0.y + xn.y*wl1.y + xn.z*wl2.y + xn.w*wl3.y;
        float lz = xn.x*wl0.z + xn.y*wl1.z + xn.z*wl2.z + xn.w*wl3.z;
        float lw = xn.x*wl0.w + xn.y*wl1.w + xn.z*wl2.w + xn.w*wl3.w;
        float rx = bl4.x + br4.x + xn.x*wr0.x + xn.y*wr1.x + xn.z*wr2.x + xn.w*wr3.x;
        float ry = bl4.y + br4.y + xn.x*wr0.y + xn.y*wr1.y + xn.z*wr2.y + xn.w*wr3.y;
        float rz = bl4.z + br4.z + xn.x*wr0.z + xn.y*wr1.z + xn.z*wr2.z + xn.w*wr3.z;
        float rw = bl4.w + br4.w + xn.x*wr0.w + xn.y*wr1.w + xn.z*wr2.w + xn.w*wr3.w;

        half2 l01 = __floats2half2_rn(lx*av.x, ly*av.y);
        half2 l23 = __floats2half2_rn(lz*av.z, lw*av.w);
        half2 r01 = __floats2half2_rn(rx*av.x, ry*av.y);
        half2 r23 = __floats2half2_rn(rz*av.z, rw*av.w);
        uint2 ul, ur;
        ul.x = *(unsigned*)&l01; ul.y = *(unsigned*)&l23;
        ur.x = *(unsigned*)&r01; ur.y = *(unsigned*)&r23;
        xl2[n * 16 + j] = ul;
        xr2[n * 16 + j] = ur;

        float p = av.x*lx + av.y*ly + av.z*lz + av.w*lw;
        p += __shfl_xor_sync(FULL, p, 8);
        p += __shfl_xor_sync(FULL, p, 4);
        p += __shfl_xor_sync(FULL, p, 2);
        p += __shfl_xor_sync(FULL, p, 1);

        if (j == 0) {
            float w = __expf(0.6f * p);
            g_w[n] = w;
            g_xw[n] = make_float4(w*xn.x, w*xn.y, w*xn.z, w*xn.w);
            g_acc[n] = make_float4(0.f, 0.f, 0.f, 0.f);
            g_den[n] = 0.f;
        }
    }
}

// -------- kernel 3: edge-parallel attention (verbatim R7 hot loop) --------
__global__ void __launch_bounds__(256)
k_edge(const int* __restrict__ ei, const float* __restrict__ att) {
    int tid  = blockIdx.x * blockDim.x + threadIdx.x;
    int lane = threadIdx.x & 31;
    int sub  = lane >> 3;
    int k    = lane & 7;

    float4 a0 = ((const float4*)att)[2*k];
    float4 a1 = ((const float4*)att)[2*k + 1];
    unsigned m0 = (a0.x < 0.f ? 0x8000u : 0u) | (a0.y < 0.f ? 0x80000000u : 0u);
    unsigned m1 = (a0.z < 0.f ? 0x8000u : 0u) | (a0.w < 0.f ? 0x80000000u : 0u);
    unsigned m2 = (a1.x < 0.f ? 0x8000u : 0u) | (a1.y < 0.f ? 0x80000000u : 0u);
    unsigned m3 = (a1.z < 0.f ? 0x8000u : 0u) | (a1.w < 0.f ? 0x80000000u : 0u);

    int warpId = tid >> 5;
    const int NW = (EDGE_BLOCKS * 256) >> 5;
    const int NQ = N_EDGES / 4;

    for (int quad = warpId; quad < NQ; quad += NW) {
        int e   = quad * 4 + sub;
        int src = ei[e];
        int dst = ei[N_EDGES + e];

        uint4 A = g_xl16[src * 8 + k];
        uint4 B = g_xr16[dst * 8 + k];

        unsigned h0, h1, h2, h3;
        asm("add.rn.f16x2 %0, %1, %2;" : "=r"(h0) : "r"(A.x), "r"(B.x));
        asm("add.rn.f16x2 %0, %1, %2;" : "=r"(h1) : "r"(A.y), "r"(B.y));
        asm("add.rn.f16x2 %0, %1, %2;" : "=r"(h2) : "r"(A.z), "r"(B.z));
        asm("add.rn.f16x2 %0, %1, %2;" : "=r"(h3) : "r"(A.w), "r"(B.w));
        h0 = (h0 & 0x7FFF7FFFu) ^ m0;
        h1 = (h1 & 0x7FFF7FFFu) ^ m1;
        h2 = (h2 & 0x7FFF7FFFu) ^ m2;
        h3 = (h3 & 0x7FFF7FFFu) ^ m3;
        unsigned s0, s1;
        asm("add.rn.f16x2 %0, %1, %2;" : "=r"(s0) : "r"(h0), "r"(h1));
        asm("add.rn.f16x2 %0, %1, %2;" : "=r"(s1) : "r"(h2), "r"(h3));
        float2 f0 = __half22float2(*(half2*)&s0);
        float2 f1 = __half22float2(*(half2*)&s1);
        float eabs = (f0.x + f0.y) + (f1.x + f1.y);

        eabs += __shfl_xor_sync(FULL, eabs, 4);
        eabs += __shfl_xor_sync(FULL, eabs, 2);
        eabs += __shfl_xor_sync(FULL, eabs, 1);

        if (k == 0) {
            float4 xw = g_xw[src];
            float  w  = g_w[src];
            float t  = __expf(0.4f * eabs);
            float ex = t * w;
            float* accp = (float*)&g_acc[dst];
            asm volatile("red.global.add.v4.f32 [%0], {%1,%2,%3,%4};"
                         :: "l"(accp), "f"(t*xw.x), "f"(t*xw.y), "f"(t*xw.z), "f"(t*xw.w)
                         : "memory");
            asm volatile("red.global.add.f32 [%0], %1;"
                         :: "l"(&g_den[dst]), "f"(ex) : "memory");
        }
    }
}

// -------- kernel 4: node finalize + LN/pool stats, separable, 8 nodes/warp --------
__global__ void __launch_bounds__(256)
k_node(const float* __restrict__ W_l, const float* __restrict__ b_l,
       const float* __restrict__ conv_bias,
       const float* __restrict__ ln_w, const float* __restrict__ lin_w,
       const int* __restrict__ batch) {
    __shared__ float sSum, sSq;
    int tid = threadIdx.x;
    if (tid == 0) { sSum = 0.f; sSq = 0.f; }
    __syncthreads();

    int lane = tid & 31;
    int warpId = (blockIdx.x * blockDim.x + tid) >> 5;
    int n0 = warpId * NODE_CHUNK;
    int c = lane;

    // per-lane channel constants (load once)
    float W0a = W_l[c],        W1a = W_l[64 + c],  W2a = W_l[128 + c],  W3a = W_l[192 + c];
    float W0b = W_l[c + 32],   W1b = W_l[96 + c],  W2b = W_l[160 + c],  W3b = W_l[224 + c];
    float bla = b_l[c],        blb = b_l[c + 32];
    float cba = conv_bias[c],  cbb = conv_bias[c + 32];
    float wta = ln_w[c] * lin_w[c];
    float wtb = ln_w[c + 32] * lin_w[c + 32];

    float accS = 0.f, accQ = 0.f, tAcc = 0.f;
    int   cnt = 0, curG = 0;

    if (n0 < N_NODES) {
        int nl = n0 + (lane & (NODE_CHUNK - 1));
        bool okl = nl < N_NODES;
        float den_l  = okl ? g_den[nl]   : 0.f;        // coalesced (8 distinct)
        int   g_lv   = okl ? batch[nl]   : 0;
        float invd_l = den_l > 0.f ? 1.f / den_l : 0.f;  // one rcp per node

        curG = __shfl_sync(FULL, g_lv, 0);
        int m = min(NODE_CHUNK, N_NODES - n0);

        #pragma unroll
        for (int i = 0; i < NODE_CHUNK; i++) {
            if (i >= m) break;
            float invd = __shfl_sync(FULL, invd_l, i);
            int   g    = __shfl_sync(FULL, g_lv, i);
            float bsel = invd > 0.f ? 1.f : 0.f;

            if (g != curG) {   // warp-uniform, rare (graph every ~1562 nodes)
                float tw = tAcc;
                #pragma unroll
                for (int off = 16; off > 0; off >>= 1)
                    tw += __shfl_xor_sync(FULL, tw, off);
                if (lane == 0) {
                    atomicAdd(&g_S[curG], (double)tw);
                    atomicAdd(&g_cnt[curG], cnt);
                }
                tAcc = 0.f; cnt = 0; curG = g;
            }

            float4 acc = g_acc[n0 + i];   // 16B broadcast
            float oa = acc.x*W0a + acc.y*W1a + acc.z*W2a + acc.w*W3a;
            float ob = acc.x*W0b + acc.y*W1b + acc.z*W2b + acc.w*W3b;
            float va = fmaxf(fmaf(oa, invd, fmaf(bsel, bla, cba)), 0.f);
            float vb = fmaxf(fmaf(ob, invd, fmaf(bsel, blb, cbb)), 0.f);

            accS += va + vb;
            accQ += va*va + vb*vb;
            tAcc += va*wta + vb*wtb;
            cnt++;
        }

        // final per-graph flush
        float tw = tAcc;
        #pragma unroll
        for (int off = 16; off > 0; off >>= 1)
            tw += __shfl_xor_sync(FULL, tw, off);
        if (lane == 0 && cnt > 0) {
            atomicAdd(&g_S[curG], (double)tw);
            atomicAdd(&g_cnt[curG], cnt);
        }
    }

    // LN stats: warp reduce then block flush
    #pragma unroll
    for (int off = 16; off > 0; off >>= 1) {
        accS += __shfl_xor_sync(FULL, accS, off);
        accQ += __shfl_xor_sync(FULL, accQ, off);
    }
    if (lane == 0) {
        atomicAdd(&sSum, accS);
        atomicAdd(&sSq,  accQ);
    }
    __syncthreads();
    if (tid == 0) {
        atomicAdd(&g_sum, (double)sSum);
        atomicAdd(&g_sq,  (double)sSq);
    }
}

// -------- kernel 5: final scalar combine + sigmoid --------
__global__ void k_final(float* __restrict__ out) {
    int t = threadIdx.x;
    double Ntot = (double)N_NODES * HID;
    double mu_d  = g_sum / Ntot;
    double var_d = g_sq / Ntot - mu_d * mu_d;
    float mu  = (float)mu_d;
    float inv = rsqrtf((float)var_d + LN_EPS);

    float cnt = fmaxf((float)g_cnt[t], 1.f);
    float y = inv * ((float)g_S[t] / cnt - mu * g_sW) + g_sB;
    out[t] = 1.f / (1.f + __expf(-y));
}

extern "C" void kernel_launch(void* const* d_in, const int* in_sizes, int n_in,
                              void* d_out, int out_size) {
    const float* x         = (const float*)d_in[0];
    const int*   ei        = (const int*)  d_in[1];
    const int*   batch     = (const int*)  d_in[2];
    const float* W_l       = (const float*)d_in[3];
    const float* b_l       = (const float*)d_in[4];
    const float* W_r       = (const float*)d_in[5];
    const float* b_r       = (const float*)d_in[6];
    const float* att       = (const float*)d_in[7];
    const float* conv_bias = (const float*)d_in[8];
    const float* ln_w      = (const float*)d_in[9];
    const float* ln_b      = (const float*)d_in[10];
    const float* lin_w     = (const float*)d_in[11];
    const float* lin_b     = (const float*)d_in[12];
    float* out = (float*)d_out;

    k_const<<<1, 32>>>(W_l, att, ln_w, ln_b, lin_w, lin_b);
    k_prehalf<<<PRE_BLOCKS, 256>>>(x, W_l, W_r, att, b_l, b_r);
    k_edge<<<EDGE_BLOCKS, 256>>>(ei, att);
    k_node<<<NODE_BLOCKS, 256>>>(W_l, b_l, conv_bias, ln_w, lin_w, batch);
    k_final<<<1, N_GRAPHS>>>(out);
}

// round 14
// speedup vs baseline: 1.1336x; 1.1336x over previous
#include <cuda_runtime.h>
#include <cuda_fp16.h>
#include <cuda_bf16.h>

#define N_NODES  100000
#define N_EDGES  1600000
#define N_GRAPHS 64
#define HID      64
#define LN_EPS   1e-5f
#define FULL     0xffffffffu
#define EDGE_BLOCKS 1184
#define PRE_BLOCKS  1184
#define NODE_WARPS  ((N_NODES + 31) / 32)              // 3125
#define NODE_BLOCKS ((NODE_WARPS + 7) / 8)             // 391

// -------- persistent device scratch (R7 layout — proven fastest) --------
__device__ uint4  g_xl16[N_NODES * 8];    // att ⊙ (x@W_l), fp16, 8 ch per uint4
__device__ uint4  g_xr16[N_NODES * 8];    // att ⊙ (x@W_r + b_l + b_r), fp16
__device__ float4 g_xw[N_NODES];          // exp(0.6*adl[n]) * x[n]
__device__ float  g_w [N_NODES];          // exp(0.6*adl[n])
__device__ float4 g_acc[N_NODES];         // sum_e t * xw[src]
__device__ float  g_den[N_NODES];         // sum_e ex
__device__ float4 g_wal;                  // W_l^T att
__device__ float  g_sW, g_sB;
__device__ double g_S[N_GRAPHS];
__device__ int    g_cnt[N_GRAPHS];
__device__ double g_sum, g_sq;

// -------- kernel 1: tiny constants (one warp) --------
__global__ void k_const(const float* __restrict__ W_l, const float* __restrict__ att,
                        const float* __restrict__ ln_w, const float* __restrict__ ln_b,
                        const float* __restrict__ lin_w, const float* __restrict__ lin_b) {
    int c = threadIdx.x;
    float a0 = att[c], a1 = att[c + 32];
    float p0 = W_l[0*64+c]*a0 + W_l[0*64+c+32]*a1;
    float p1 = W_l[1*64+c]*a0 + W_l[1*64+c+32]*a1;
    float p2 = W_l[2*64+c]*a0 + W_l[2*64+c+32]*a1;
    float p3 = W_l[3*64+c]*a0 + W_l[3*64+c+32]*a1;
    float sw = ln_w[c]*lin_w[c] + ln_w[c+32]*lin_w[c+32];
    float sb = ln_b[c]*lin_w[c] + ln_b[c+32]*lin_w[c+32];
    #pragma unroll
    for (int off = 16; off > 0; off >>= 1) {
        p0 += __shfl_xor_sync(FULL, p0, off);
        p1 += __shfl_xor_sync(FULL, p1, off);
        p2 += __shfl_xor_sync(FULL, p2, off);
        p3 += __shfl_xor_sync(FULL, p3, off);
        sw += __shfl_xor_sync(FULL, sw, off);
        sb += __shfl_xor_sync(FULL, sb, off);
    }
    if (c == 0) {
        g_wal = make_float4(p0, p1, p2, p3);
        g_sW = sw;
        g_sB = sb + lin_b[0];
        g_sum = 0.0;
        g_sq  = 0.0;
    }
    if (c < N_GRAPHS) { g_S[c] = 0.0; g_cnt[c] = 0; }
    if (c + 32 < N_GRAPHS) { g_S[c + 32] = 0.0; g_cnt[c + 32] = 0; }
}

// -------- kernel 2: node projections -> fp16 + src weights + acc clear --------
// grid-stride over node pairs; warp = 2 nodes/iter; 16 lanes per node
__global__ void __launch_bounds__(256)
k_prehalf(const float* __restrict__ x,
          const float* __restrict__ W_l, const float* __restrict__ W_r,
          const float* __restrict__ att,
          const float* __restrict__ b_l, const float* __restrict__ b_r) {
    int tid  = blockIdx.x * blockDim.x + threadIdx.x;
    int lane = threadIdx.x & 31;
    int half = lane >> 4;
    int j    = lane & 15;

    const float4* x4  = (const float4*)x;
    const float4* wl4 = (const float4*)W_l;
    const float4* wr4 = (const float4*)W_r;
    float4 wl0 = wl4[j], wl1 = wl4[16 + j], wl2 = wl4[32 + j], wl3 = wl4[48 + j];
    float4 wr0 = wr4[j], wr1 = wr4[16 + j], wr2 = wr4[32 + j], wr3 = wr4[48 + j];
    float4 av  = ((const float4*)att)[j];
    float4 bl4 = ((const float4*)b_l)[j];
    float4 br4 = ((const float4*)b_r)[j];

    int warpId = tid >> 5;
    const int NW = (PRE_BLOCKS * 256) >> 5;
    uint2* xl2 = (uint2*)g_xl16;
    uint2* xr2 = (uint2*)g_xr16;

    for (int task = warpId; task < N_NODES / 2; task += NW) {
        int n = task * 2 + half;

        float4 xn = x4[n];
        float lx = xn.x*wl0.x + xn.y*wl1.x + xn.z*wl2.x + xn.w*wl3.x;
        float ly = xn.x*wl0.y + xn.y*wl1.y + xn.z*wl2.y + xn.w*wl3.y;
        float lz = xn.x*wl0.z + xn.y*wl1.z + xn.z*wl2.z + xn.w*wl3.z;
        float lw = xn.x*wl0.w + xn.y*wl1.w + xn.z*wl2.w + xn.w*wl3.w;
        float rx = bl4.x + br4.x + xn.x*wr0.x + xn.y*wr1.x + xn.z*wr2.x + xn.w*wr3.x;
        float ry = bl4.y + br4.y + xn.x*wr0.y + xn.y*wr1.y + xn.z*wr2.y + xn.w*wr3.y;
        float rz = bl4.z + br4.z + xn.x*wr0.z + xn.y*wr1.z + xn.z*wr2.z + xn.w*wr3.z;
        float rw = bl4.w + br4.w + xn.x*wr0.w + xn.y*wr1.w + xn.z*wr2.w + xn.w*wr3.w;

        half2 l01 = __floats2half2_rn(lx*av.x, ly*av.y);
        half2 l23 = __floats2half2_rn(lz*av.z, lw*av.w);
        half2 r01 = __floats2half2_rn(rx*av.x, ry*av.y);
        half2 r23 = __floats2half2_rn(rz*av.z, rw*av.w);
        uint2 ul, ur;
        ul.x = *(unsigned*)&l01; ul.y = *(unsigned*)&l23;
        ur.x = *(unsigned*)&r01; ur.y = *(unsigned*)&r23;
        xl2[n * 16 + j] = ul;
        xr2[n * 16 + j] = ur;

        float p = av.x*lx + av.y*ly + av.z*lz + av.w*lw;
        p += __shfl_xor_sync(FULL, p, 8);
        p += __shfl_xor_sync(FULL, p, 4);
        p += __shfl_xor_sync(FULL, p, 2);
        p += __shfl_xor_sync(FULL, p, 1);

        if (j == 0) {
            float w = __expf(0.6f * p);
            g_w[n] = w;
            g_xw[n] = make_float4(w*xn.x, w*xn.y, w*xn.z, w*xn.w);
            g_acc[n] = make_float4(0.f, 0.f, 0.f, 0.f);
            g_den[n] = 0.f;
        }
    }
}

// -------- kernel 3: edge-parallel attention (verbatim R7 hot loop) --------
__global__ void __launch_bounds__(256)
k_edge(const int* __restrict__ ei, const float* __restrict__ att) {
    int tid  = blockIdx.x * blockDim.x + threadIdx.x;
    int lane = threadIdx.x & 31;
    int sub  = lane >> 3;
    int k    = lane & 7;

    float4 a0 = ((const float4*)att)[2*k];
    float4 a1 = ((const float4*)att)[2*k + 1];
    unsigned m0 = (a0.x < 0.f ? 0x8000u : 0u) | (a0.y < 0.f ? 0x80000000u : 0u);
    unsigned m1 = (a0.z < 0.f ? 0x8000u : 0u) | (a0.w < 0.f ? 0x80000000u : 0u);
    unsigned m2 = (a1.x < 0.f ? 0x8000u : 0u) | (a1.y < 0.f ? 0x80000000u : 0u);
    unsigned m3 = (a1.z < 0.f ? 0x8000u : 0u) | (a1.w < 0.f ? 0x80000000u : 0u);

    int warpId = tid >> 5;
    const int NW = (EDGE_BLOCKS * 256) >> 5;
    const int NQ = N_EDGES / 4;

    for (int quad = warpId; quad < NQ; quad += NW) {
        int e   = quad * 4 + sub;
        int src = ei[e];
        int dst = ei[N_EDGES + e];

        uint4 A = g_xl16[src * 8 + k];
        uint4 B = g_xr16[dst * 8 + k];

        unsigned h0, h1, h2, h3;
        asm("add.rn.f16x2 %0, %1, %2;" : "=r"(h0) : "r"(A.x), "r"(B.x));
        asm("add.rn.f16x2 %0, %1, %2;" : "=r"(h1) : "r"(A.y), "r"(B.y));
        asm("add.rn.f16x2 %0, %1, %2;" : "=r"(h2) : "r"(A.z), "r"(B.z));
        asm("add.rn.f16x2 %0, %1, %2;" : "=r"(h3) : "r"(A.w), "r"(B.w));
        h0 = (h0 & 0x7FFF7FFFu) ^ m0;
        h1 = (h1 & 0x7FFF7FFFu) ^ m1;
        h2 = (h2 & 0x7FFF7FFFu) ^ m2;
        h3 = (h3 & 0x7FFF7FFFu) ^ m3;
        unsigned s0, s1;
        asm("add.rn.f16x2 %0, %1, %2;" : "=r"(s0) : "r"(h0), "r"(h1));
        asm("add.rn.f16x2 %0, %1, %2;" : "=r"(s1) : "r"(h2), "r"(h3));
        float2 f0 = __half22float2(*(half2*)&s0);
        float2 f1 = __half22float2(*(half2*)&s1);
        float eabs = (f0.x + f0.y) + (f1.x + f1.y);

        eabs += __shfl_xor_sync(FULL, eabs, 4);
        eabs += __shfl_xor_sync(FULL, eabs, 2);
        eabs += __shfl_xor_sync(FULL, eabs, 1);

        if (k == 0) {
            float4 xw = g_xw[src];
            float  w  = g_w[src];
            float t  = __expf(0.4f * eabs);
            float ex = t * w;
            float* accp = (float*)&g_acc[dst];
            asm volatile("red.global.add.v4.f32 [%0], {%1,%2,%3,%4};"
                         :: "l"(accp), "f"(t*xw.x), "f"(t*xw.y), "f"(t*xw.z), "f"(t*xw.w)
                         : "memory");
            asm volatile("red.global.add.f32 [%0], %1;"
                         :: "l"(&g_den[dst]), "f"(ex) : "memory");
        }
    }
}

// -------- kernel 4: node finalize + LN/pool stats, 32 nodes/warp --------
// lane i preloads g_acc[n0+i] (coalesced, parallel L2 round trips);
// loop broadcasts via shfl — no serial load chain.
__global__ void __launch_bounds__(256)
k_node(const float* __restrict__ W_l, const float* __restrict__ b_l,
       const float* __restrict__ conv_bias,
       const float* __restrict__ ln_w, const float* __restrict__ lin_w,
       const int* __restrict__ batch) {
    __shared__ float sSum, sSq;
    int tid = threadIdx.x;
    if (tid == 0) { sSum = 0.f; sSq = 0.f; }
    __syncthreads();

    int lane = tid & 31;
    int warpId = (blockIdx.x * blockDim.x + tid) >> 5;
    int n0 = warpId * 32;
    int c = lane;

    // per-lane channel constants (load once)
    float W0a = W_l[c],        W1a = W_l[64 + c],  W2a = W_l[128 + c],  W3a = W_l[192 + c];
    float W0b = W_l[c + 32],   W1b = W_l[96 + c],  W2b = W_l[160 + c],  W3b = W_l[224 + c];
    float bla = b_l[c],        blb = b_l[c + 32];
    float cba = conv_bias[c],  cbb = conv_bias[c + 32];
    float wta = ln_w[c] * lin_w[c];
    float wtb = ln_w[c + 32] * lin_w[c + 32];

    float accS = 0.f, accQ = 0.f, tAcc = 0.f;
    int   cnt = 0, curG = 0;

    if (n0 < N_NODES) {
        int nl = n0 + lane;
        bool okl = nl < N_NODES;
        // ALL per-node data loaded in parallel across lanes (coalesced)
        float4 acc_l = okl ? g_acc[nl] : make_float4(0.f, 0.f, 0.f, 0.f);
        float  den_l = okl ? g_den[nl] : 0.f;
        int    g_lv  = okl ? batch[nl] : 0;
        float invd_l = den_l > 0.f ? 1.f / den_l : 0.f;  // one rcp per node

        curG = __shfl_sync(FULL, g_lv, 0);
        int m = min(32, N_NODES - n0);

        for (int i = 0; i < m; i++) {
            float invd = __shfl_sync(FULL, invd_l, i);
            int   g    = __shfl_sync(FULL, g_lv, i);
            float ax   = __shfl_sync(FULL, acc_l.x, i);
            float ay   = __shfl_sync(FULL, acc_l.y, i);
            float az   = __shfl_sync(FULL, acc_l.z, i);
            float aw   = __shfl_sync(FULL, acc_l.w, i);
            float bsel = invd > 0.f ? 1.f : 0.f;

            if (g != curG) {   // warp-uniform, rare (~1 per warp)
                float tw = tAcc;
                #pragma unroll
                for (int off = 16; off > 0; off >>= 1)
                    tw += __shfl_xor_sync(FULL, tw, off);
                if (lane == 0) {
                    atomicAdd(&g_S[curG], (double)tw);
                    atomicAdd(&g_cnt[curG], cnt);
                }
                tAcc = 0.f; cnt = 0; curG = g;
            }

            float oa = ax*W0a + ay*W1a + az*W2a + aw*W3a;
            float ob = ax*W0b + ay*W1b + az*W2b + aw*W3b;
            float va = fmaxf(fmaf(oa, invd, fmaf(bsel, bla, cba)), 0.f);
            float vb = fmaxf(fmaf(ob, invd, fmaf(bsel, blb, cbb)), 0.f);

            accS += va + vb;
            accQ += va*va + vb*vb;
            tAcc += va*wta + vb*wtb;
            cnt++;
        }

        // final per-graph flush
        float tw = tAcc;
        #pragma unroll
        for (int off = 16; off > 0; off >>= 1)
            tw += __shfl_xor_sync(FULL, tw, off);
        if (lane == 0 && cnt > 0) {
            atomicAdd(&g_S[curG], (double)tw);
            atomicAdd(&g_cnt[curG], cnt);
        }
    }

    // LN stats: warp reduce then block flush
    #pragma unroll
    for (int off = 16; off > 0; off >>= 1) {
        accS += __shfl_xor_sync(FULL, accS, off);
        accQ += __shfl_xor_sync(FULL, accQ, off);
    }
    if (lane == 0) {
        atomicAdd(&sSum, accS);
        atomicAdd(&sSq,  accQ);
    }
    __syncthreads();
    if (tid == 0) {
        atomicAdd(&g_sum, (double)sSum);
        atomicAdd(&g_sq,  (double)sSq);
    }
}

// -------- kernel 5: final scalar combine + sigmoid --------
__global__ void k_final(float* __restrict__ out) {
    int t = threadIdx.x;
    double Ntot = (double)N_NODES * HID;
    double mu_d  = g_sum / Ntot;
    double var_d = g_sq / Ntot - mu_d * mu_d;
    float mu  = (float)mu_d;
    float inv = rsqrtf((float)var_d + LN_EPS);

    float cnt = fmaxf((float)g_cnt[t], 1.f);
    float y = inv * ((float)g_S[t] / cnt - mu * g_sW) + g_sB;
    out[t] = 1.f / (1.f + __expf(-y));
}

extern "C" void kernel_launch(void* const* d_in, const int* in_sizes, int n_in,
                              void* d_out, int out_size) {
    const float* x         = (const float*)d_in[0];
    const int*   ei        = (const int*)  d_in[1];
    const int*   batch     = (const int*)  d_in[2];
    const float* W_l       = (const float*)d_in[3];
    const float* b_l       = (const float*)d_in[4];
    const float* W_r       = (const float*)d_in[5];
    const float* b_r       = (const float*)d_in[6];
    const float* att       = (const float*)d_in[7];
    const float* conv_bias = (const float*)d_in[8];
    const float* ln_w      = (const float*)d_in[9];
    const float* ln_b      = (const float*)d_in[10];
    const float* lin_w     = (const float*)d_in[11];
    const float* lin_b     = (const float*)d_in[12];
    float* out = (float*)d_out;

    k_const<<<1, 32>>>(W_l, att, ln_w, ln_b, lin_w, lin_b);
    k_prehalf<<<PRE_BLOCKS, 256>>>(x, W_l, W_r, att, b_l, b_r);
    k_edge<<<EDGE_BLOCKS, 256>>>(ei, att);
    k_node<<<NODE_BLOCKS, 256>>>(W_l, b_l, conv_bias, ln_w, lin_w, batch);
    k_final<<<1, N_GRAPHS>>>(out);
}

// round 15
// speedup vs baseline: 1.1962x; 1.0553x over previous
#include <cuda_runtime.h>
#include <cuda_fp16.h>
#include <cuda_bf16.h>

#define N_NODES  100000
#define N_EDGES  1600000
#define N_GRAPHS 64
#define HID      64
#define LN_EPS   1e-5f
#define FULL     0xffffffffu
#define EDGE_BLOCKS 1184
#define PRE_BLOCKS  1184
#define NODE_WARPS  ((N_NODES + 31) / 32)              // 3125
#define NODE_BLOCKS ((NODE_WARPS + 7) / 8)             // 391

// -------- persistent device scratch --------
__device__ unsigned g_xl8[N_NODES * 16];  // att ⊙ (x@W_l), e4m3, 64B/row
__device__ unsigned g_xr8[N_NODES * 16];  // att ⊙ (x@W_r + b_l + b_r), e4m3
__device__ float4 g_xw[N_NODES];          // exp(0.6*adl[n]) * x[n]
__device__ float  g_w [N_NODES];          // exp(0.6*adl[n])
__device__ float4 g_acc[N_NODES];         // sum_e t * xw[src]
__device__ float  g_den[N_NODES];         // sum_e ex
__device__ float  g_sW, g_sB;
__device__ double g_S[N_GRAPHS];
__device__ int    g_cnt[N_GRAPHS];
__device__ double g_sum, g_sq;

// -------- kernel 1: tiny constants (one warp) --------
__global__ void k_const(const float* __restrict__ ln_w, const float* __restrict__ ln_b,
                        const float* __restrict__ lin_w, const float* __restrict__ lin_b) {
    int c = threadIdx.x;
    float sw = ln_w[c]*lin_w[c] + ln_w[c+32]*lin_w[c+32];
    float sb = ln_b[c]*lin_w[c] + ln_b[c+32]*lin_w[c+32];
    #pragma unroll
    for (int off = 16; off > 0; off >>= 1) {
        sw += __shfl_xor_sync(FULL, sw, off);
        sb += __shfl_xor_sync(FULL, sb, off);
    }
    if (c == 0) {
        g_sW = sw;
        g_sB = sb + lin_b[0];
        g_sum = 0.0;
        g_sq  = 0.0;
    }
    if (c < N_GRAPHS) { g_S[c] = 0.0; g_cnt[c] = 0; }
    if (c + 32 < N_GRAPHS) { g_S[c + 32] = 0.0; g_cnt[c + 32] = 0; }
}

// -------- kernel 2: node projections -> e4m3 + src weights + acc clear --------
// grid-stride; warp = 2 nodes/iter; 16 lanes per node; lane j owns ch [4j,4j+4)
__global__ void __launch_bounds__(256)
k_prehalf(const float* __restrict__ x,
          const float* __restrict__ W_l, const float* __restrict__ W_r,
          const float* __restrict__ att,
          const float* __restrict__ b_l, const float* __restrict__ b_r) {
    int tid  = blockIdx.x * blockDim.x + threadIdx.x;
    int lane = threadIdx.x & 31;
    int half = lane >> 4;
    int j    = lane & 15;

    const float4* x4  = (const float4*)x;
    const float4* wl4 = (const float4*)W_l;
    const float4* wr4 = (const float4*)W_r;
    float4 wl0 = wl4[j], wl1 = wl4[16 + j], wl2 = wl4[32 + j], wl3 = wl4[48 + j];
    float4 wr0 = wr4[j], wr1 = wr4[16 + j], wr2 = wr4[32 + j], wr3 = wr4[48 + j];
    float4 av  = ((const float4*)att)[j];
    float4 bl4 = ((const float4*)b_l)[j];
    float4 br4 = ((const float4*)b_r)[j];

    int warpId = tid >> 5;
    const int NW = (PRE_BLOCKS * 256) >> 5;

    for (int task = warpId; task < N_NODES / 2; task += NW) {
        int n = task * 2 + half;

        float4 xn = x4[n];
        float lx = xn.x*wl0.x + xn.y*wl1.x + xn.z*wl2.x + xn.w*wl3.x;
        float ly = xn.x*wl0.y + xn.y*wl1.y + xn.z*wl2.y + xn.w*wl3.y;
        float lz = xn.x*wl0.z + xn.y*wl1.z + xn.z*wl2.z + xn.w*wl3.z;
        float lw = xn.x*wl0.w + xn.y*wl1.w + xn.z*wl2.w + xn.w*wl3.w;
        float rx = bl4.x + br4.x + xn.x*wr0.x + xn.y*wr1.x + xn.z*wr2.x + xn.w*wr3.x;
        float ry = bl4.y + br4.y + xn.x*wr0.y + xn.y*wr1.y + xn.z*wr2.y + xn.w*wr3.y;
        float rz = bl4.z + br4.z + xn.x*wr0.z + xn.y*wr1.z + xn.z*wr2.z + xn.w*wr3.z;
        float rw = bl4.w + br4.w + xn.x*wr0.w + xn.y*wr1.w + xn.z*wr2.w + xn.w*wr3.w;

        // att-folded values -> fp16 pairs -> e4m3x2 pairs -> one u32 (4 channels)
        half2 l01 = __floats2half2_rn(lx*av.x, ly*av.y);
        half2 l23 = __floats2half2_rn(lz*av.z, lw*av.w);
        half2 r01 = __floats2half2_rn(rx*av.x, ry*av.y);
        half2 r23 = __floats2half2_rn(rz*av.z, rw*av.w);
        unsigned short pa0, pa1, pb0, pb1;
        asm("cvt.rn.satfinite.e4m3x2.f16x2 %0, %1;" : "=h"(pa0) : "r"(*(unsigned*)&l01));
        asm("cvt.rn.satfinite.e4m3x2.f16x2 %0, %1;" : "=h"(pa1) : "r"(*(unsigned*)&l23));
        asm("cvt.rn.satfinite.e4m3x2.f16x2 %0, %1;" : "=h"(pb0) : "r"(*(unsigned*)&r01));
        asm("cvt.rn.satfinite.e4m3x2.f16x2 %0, %1;" : "=h"(pb1) : "r"(*(unsigned*)&r23));
        unsigned ua, ub;
        asm("mov.b32 %0, {%1,%2};" : "=r"(ua) : "h"(pa0), "h"(pa1));
        asm("mov.b32 %0, {%1,%2};" : "=r"(ub) : "h"(pb0), "h"(pb1));
        g_xl8[n * 16 + j] = ua;
        g_xr8[n * 16 + j] = ub;

        // adl = att.(x@W_l): exact fp32 reduce over 16 lanes of this node
        float p = av.x*lx + av.y*ly + av.z*lz + av.w*lw;
        p += __shfl_xor_sync(FULL, p, 8);
        p += __shfl_xor_sync(FULL, p, 4);
        p += __shfl_xor_sync(FULL, p, 2);
        p += __shfl_xor_sync(FULL, p, 1);

        if (j == 0) {
            float w = __expf(0.6f * p);   // dst-side linear term cancels in softmax
            g_w[n] = w;
            g_xw[n] = make_float4(w*xn.x, w*xn.y, w*xn.z, w*xn.w);
            g_acc[n] = make_float4(0.f, 0.f, 0.f, 0.f);
            g_den[n] = 0.f;
        }
    }
}

// -------- kernel 3: edge-parallel attention, e4m3 rows, 4 lanes/edge --------
// lane: sub = lane>>2 selects edge (8/warp), k2 = lane&3 owns ch [16k2,16k2+16)
__global__ void __launch_bounds__(256)
k_edge(const int* __restrict__ ei, const float* __restrict__ att) {
    int tid  = blockIdx.x * blockDim.x + threadIdx.x;
    int lane = threadIdx.x & 31;
    int sub  = lane >> 2;
    int k2   = lane & 3;

    // sign-fold masks for this lane's 16 channels (8 half2 pairs)
    const float4* att4 = (const float4*)att;
    unsigned msk[8];
    #pragma unroll
    for (int i = 0; i < 4; i++) {
        float4 a = att4[4*k2 + i];
        msk[2*i]   = (a.x < 0.f ? 0x8000u : 0u) | (a.y < 0.f ? 0x80000000u : 0u);
        msk[2*i+1] = (a.z < 0.f ? 0x8000u : 0u) | (a.w < 0.f ? 0x80000000u : 0u);
    }

    const uint4* xl4 = (const uint4*)g_xl8;   // row = 4 uint4
    const uint4* xr4 = (const uint4*)g_xr8;

    int warpId = tid >> 5;
    const int NW = (EDGE_BLOCKS * 256) >> 5;
    const int NO = N_EDGES / 8;

    for (int oct = warpId; oct < NO; oct += NW) {
        int e   = oct * 8 + sub;
        int src = ei[e];
        int dst = ei[N_EDGES + e];

        uint4 A = xl4[src * 4 + k2];
        uint4 B = xr4[dst * 4 + k2];

        unsigned s0 = 0u, s1 = 0u;   // two half2 accumulators (start at +0,+0)
        #pragma unroll
        for (int q = 0; q < 4; q++) {
            unsigned a = (q == 0) ? A.x : (q == 1) ? A.y : (q == 2) ? A.z : A.w;
            unsigned b = (q == 0) ? B.x : (q == 1) ? B.y : (q == 2) ? B.z : B.w;
            unsigned short alo, ahi, blo, bhi;
            asm("mov.b32 {%0,%1}, %2;" : "=h"(alo), "=h"(ahi) : "r"(a));
            asm("mov.b32 {%0,%1}, %2;" : "=h"(blo), "=h"(bhi) : "r"(b));
            unsigned ha0, ha1, hb0, hb1, h0, h1;
            asm("cvt.rn.f16x2.e4m3x2 %0, %1;" : "=r"(ha0) : "h"(alo));
            asm("cvt.rn.f16x2.e4m3x2 %0, %1;" : "=r"(ha1) : "h"(ahi));
            asm("cvt.rn.f16x2.e4m3x2 %0, %1;" : "=r"(hb0) : "h"(blo));
            asm("cvt.rn.f16x2.e4m3x2 %0, %1;" : "=r"(hb1) : "h"(bhi));
            asm("add.rn.f16x2 %0, %1, %2;" : "=r"(h0) : "r"(ha0), "r"(hb0));
            asm("add.rn.f16x2 %0, %1, %2;" : "=r"(h1) : "r"(ha1), "r"(hb1));
            h0 = (h0 & 0x7FFF7FFFu) ^ msk[2*q];       // att_c * |h_c| signed
            h1 = (h1 & 0x7FFF7FFFu) ^ msk[2*q + 1];
            asm("add.rn.f16x2 %0, %1, %2;" : "=r"(s0) : "r"(s0), "r"(h0));
            asm("add.rn.f16x2 %0, %1, %2;" : "=r"(s1) : "r"(s1), "r"(h1));
        }
        unsigned st;
        asm("add.rn.f16x2 %0, %1, %2;" : "=r"(st) : "r"(s0), "r"(s1));
        float2 f = __half22float2(*(half2*)&st);
        float eabs = f.x + f.y;

        eabs += __shfl_xor_sync(FULL, eabs, 2);   // reduce within 4-lane group
        eabs += __shfl_xor_sync(FULL, eabs, 1);

        if (k2 == 0) {
            float4 xw = g_xw[src];
            float  w  = g_w[src];
            float t  = __expf(0.4f * eabs);
            float ex = t * w;                     // full (shift-free) ex
            float* accp = (float*)&g_acc[dst];
            asm volatile("red.global.add.v4.f32 [%0], {%1,%2,%3,%4};"
                         :: "l"(accp), "f"(t*xw.x), "f"(t*xw.y), "f"(t*xw.z), "f"(t*xw.w)
                         : "memory");
            asm volatile("red.global.add.f32 [%0], %1;"
                         :: "l"(&g_den[dst]), "f"(ex) : "memory");
        }
    }
}

// -------- kernel 4: node finalize + LN/pool stats, 32 nodes/warp (R14) --------
__global__ void __launch_bounds__(256)
k_node(const float* __restrict__ W_l, const float* __restrict__ b_l,
       const float* __restrict__ conv_bias,
       const float* __restrict__ ln_w, const float* __restrict__ lin_w,
       const int* __restrict__ batch) {
    __shared__ float sSum, sSq;
    int tid = threadIdx.x;
    if (tid == 0) { sSum = 0.f; sSq = 0.f; }
    __syncthreads();

    int lane = tid & 31;
    int warpId = (blockIdx.x * blockDim.x + tid) >> 5;
    int n0 = warpId * 32;
    int c = lane;

    float W0a = W_l[c],        W1a = W_l[64 + c],  W2a = W_l[128 + c],  W3a = W_l[192 + c];
    float W0b = W_l[c + 32],   W1b = W_l[96 + c],  W2b = W_l[160 + c],  W3b = W_l[224 + c];
    float bla = b_l[c],        blb = b_l[c + 32];
    float cba = conv_bias[c],  cbb = conv_bias[c + 32];
    float wta = ln_w[c] * lin_w[c];
    float wtb = ln_w[c + 32] * lin_w[c + 32];

    float accS = 0.f, accQ = 0.f, tAcc = 0.f;
    int   cnt = 0, curG = 0;

    if (n0 < N_NODES) {
        int nl = n0 + lane;
        bool okl = nl < N_NODES;
        float4 acc_l = okl ? g_acc[nl] : make_float4(0.f, 0.f, 0.f, 0.f);
        float  den_l = okl ? g_den[nl] : 0.f;
        int    g_lv  = okl ? batch[nl] : 0;
        float invd_l = den_l > 0.f ? 1.f / den_l : 0.f;

        curG = __shfl_sync(FULL, g_lv, 0);
        int m = min(32, N_NODES - n0);

        for (int i = 0; i < m; i++) {
            float invd = __shfl_sync(FULL, invd_l, i);
            int   g    = __shfl_sync(FULL, g_lv, i);
            float ax   = __shfl_sync(FULL, acc_l.x, i);
            float ay   = __shfl_sync(FULL, acc_l.y, i);
            float az   = __shfl_sync(FULL, acc_l.z, i);
            float aw   = __shfl_sync(FULL, acc_l.w, i);
            float bsel = invd > 0.f ? 1.f : 0.f;

            if (g != curG) {
                float tw = tAcc;
                #pragma unroll
                for (int off = 16; off > 0; off >>= 1)
                    tw += __shfl_xor_sync(FULL, tw, off);
                if (lane == 0) {
                    atomicAdd(&g_S[curG], (double)tw);
                    atomicAdd(&g_cnt[curG], cnt);
                }
                tAcc = 0.f; cnt = 0; curG = g;
            }

            float oa = ax*W0a + ay*W1a + az*W2a + aw*W3a;
            float ob = ax*W0b + ay*W1b + az*W2b + aw*W3b;
            float va = fmaxf(fmaf(oa, invd, fmaf(bsel, bla, cba)), 0.f);
            float vb = fmaxf(fmaf(ob, invd, fmaf(bsel, blb, cbb)), 0.f);

            accS += va + vb;
            accQ += va*va + vb*vb;
            tAcc += va*wta + vb*wtb;
            cnt++;
        }

        float tw = tAcc;
        #pragma unroll
        for (int off = 16; off > 0; off >>= 1)
            tw += __shfl_xor_sync(FULL, tw, off);
        if (lane == 0 && cnt > 0) {
            atomicAdd(&g_S[curG], (double)tw);
            atomicAdd(&g_cnt[curG], cnt);
        }
    }

    #pragma unroll
    for (int off = 16; off > 0; off >>= 1) {
        accS += __shfl_xor_sync(FULL, accS, off);
        accQ += __shfl_xor_sync(FULL, accQ, off);
    }
    if (lane == 0) {
        atomicAdd(&sSum, accS);
        atomicAdd(&sSq,  accQ);
    }
    __syncthreads();
    if (tid == 0) {
        atomicAdd(&g_sum, (double)sSum);
        atomicAdd(&g_sq,  (double)sSq);
    }
}

// -------- kernel 5: final scalar combine + sigmoid --------
__global__ void k_final(float* __restrict__ out) {
    int t = threadIdx.x;
    double Ntot = (double)N_NODES * HID;
    double mu_d  = g_sum / Ntot;
    double var_d = g_sq / Ntot - mu_d * mu_d;
    float mu  = (float)mu_d;
    float inv = rsqrtf((float)var_d + LN_EPS);

    float cnt = fmaxf((float)g_cnt[t], 1.f);
    float y = inv * ((float)g_S[t] / cnt - mu * g_sW) + g_sB;
    out[t] = 1.f / (1.f + __expf(-y));
}

extern "C" void kernel_launch(void* const* d_in, const int* in_sizes, int n_in,
                              void* d_out, int out_size) {
    const float* x         = (const float*)d_in[0];
    const int*   ei        = (const int*)  d_in[1];
    const int*   batch     = (const int*)  d_in[2];
    const float* W_l       = (const float*)d_in[3];
    const float* b_l       = (const float*)d_in[4];
    const float* W_r       = (const float*)d_in[5];
    const float* b_r       = (const float*)d_in[6];
    const float* att       = (const float*)d_in[7];
    const float* conv_bias = (const float*)d_in[8];
    const float* ln_w      = (const float*)d_in[9];
    const float* ln_b      = (const float*)d_in[10];
    const float* lin_w     = (const float*)d_in[11];
    const float* lin_b     = (const float*)d_in[12];
    float* out = (float*)d_out;

    k_const<<<1, 32>>>(ln_w, ln_b, lin_w, lin_b);
    k_prehalf<<<PRE_BLOCKS, 256>>>(x, W_l, W_r, att, b_l, b_r);
    k_edge<<<EDGE_BLOCKS, 256>>>(ei, att);
    k_node<<<NODE_BLOCKS, 256>>>(W_l, b_l, conv_bias, ln_w, lin_w, batch);
    k_final<<<1, N_GRAPHS>>>(out);
}

// round 16
// speedup vs baseline: 1.2362x; 1.0335x over previous
#include <cuda_runtime.h>
#include <cuda_fp16.h>
#include <cuda_bf16.h>

#define N_NODES  100000
#define N_EDGES  1600000
#define N_GRAPHS 64
#define HID      64
#define LN_EPS   1e-5f
#define FULL     0xffffffffu
#define EDGE_BLOCKS 1184
#define PRE_BLOCKS  1184
#define NODE_WARPS  ((N_NODES + 31) / 32)              // 3125
#define NODE_BLOCKS ((NODE_WARPS + 7) / 8)             // 391

// -------- persistent device scratch --------
__device__ unsigned g_xl8[N_NODES * 16];  // att ⊙ (x@W_l), e4m3, 64B/row
__device__ unsigned g_xr8[N_NODES * 16];  // att ⊙ (x@W_r + b_l + b_r), e4m3
__device__ __align__(32) float g_xww[N_NODES * 8];    // [w*x (4), w, pad3] one sector
__device__ __align__(32) float g_accden[N_NODES * 8]; // [acc (4), den, pad3] one sector
__device__ float  g_sW, g_sB;
__device__ double g_S[N_GRAPHS];
__device__ int    g_cnt[N_GRAPHS];
__device__ double g_sum, g_sq;

// -------- kernel 1: tiny constants (one warp) --------
__global__ void k_const(const float* __restrict__ ln_w, const float* __restrict__ ln_b,
                        const float* __restrict__ lin_w, const float* __restrict__ lin_b) {
    int c = threadIdx.x;
    float sw = ln_w[c]*lin_w[c] + ln_w[c+32]*lin_w[c+32];
    float sb = ln_b[c]*lin_w[c] + ln_b[c+32]*lin_w[c+32];
    #pragma unroll
    for (int off = 16; off > 0; off >>= 1) {
        sw += __shfl_xor_sync(FULL, sw, off);
        sb += __shfl_xor_sync(FULL, sb, off);
    }
    if (c == 0) {
        g_sW = sw;
        g_sB = sb + lin_b[0];
        g_sum = 0.0;
        g_sq  = 0.0;
    }
    if (c < N_GRAPHS) { g_S[c] = 0.0; g_cnt[c] = 0; }
    if (c + 32 < N_GRAPHS) { g_S[c + 32] = 0.0; g_cnt[c + 32] = 0; }
}

// -------- kernel 2: node projections -> e4m3 + src weights + acc clear --------
// grid-stride; warp = 2 nodes/iter; 16 lanes per node; lane j owns ch [4j,4j+4)
__global__ void __launch_bounds__(256)
k_prehalf(const float* __restrict__ x,
          const float* __restrict__ W_l, const float* __restrict__ W_r,
          const float* __restrict__ att,
          const float* __restrict__ b_l, const float* __restrict__ b_r) {
    int tid  = blockIdx.x * blockDim.x + threadIdx.x;
    int lane = threadIdx.x & 31;
    int half = lane >> 4;
    int j    = lane & 15;

    const float4* x4  = (const float4*)x;
    const float4* wl4 = (const float4*)W_l;
    const float4* wr4 = (const float4*)W_r;
    float4 wl0 = wl4[j], wl1 = wl4[16 + j], wl2 = wl4[32 + j], wl3 = wl4[48 + j];
    float4 wr0 = wr4[j], wr1 = wr4[16 + j], wr2 = wr4[32 + j], wr3 = wr4[48 + j];
    float4 av  = ((const float4*)att)[j];
    float4 bl4 = ((const float4*)b_l)[j];
    float4 br4 = ((const float4*)b_r)[j];

    int warpId = tid >> 5;
    const int NW = (PRE_BLOCKS * 256) >> 5;

    for (int task = warpId; task < N_NODES / 2; task += NW) {
        int n = task * 2 + half;

        float4 xn = x4[n];
        float lx = xn.x*wl0.x + xn.y*wl1.x + xn.z*wl2.x + xn.w*wl3.x;
        float ly = xn.x*wl0.y + xn.y*wl1.y + xn.z*wl2.y + xn.w*wl3.y;
        float lz = xn.x*wl0.z + xn.y*wl1.z + xn.z*wl2.z + xn.w*wl3.z;
        float lw = xn.x*wl0.w + xn.y*wl1.w + xn.z*wl2.w + xn.w*wl3.w;
        float rx = bl4.x + br4.x + xn.x*wr0.x + xn.y*wr1.x + xn.z*wr2.x + xn.w*wr3.x;
        float ry = bl4.y + br4.y + xn.x*wr0.y + xn.y*wr1.y + xn.z*wr2.y + xn.w*wr3.y;
        float rz = bl4.z + br4.z + xn.x*wr0.z + xn.y*wr1.z + xn.z*wr2.z + xn.w*wr3.z;
        float rw = bl4.w + br4.w + xn.x*wr0.w + xn.y*wr1.w + xn.z*wr2.w + xn.w*wr3.w;

        // att-folded values -> fp16 pairs -> e4m3x2 pairs -> one u32 (4 channels)
        half2 l01 = __floats2half2_rn(lx*av.x, ly*av.y);
        half2 l23 = __floats2half2_rn(lz*av.z, lw*av.w);
        half2 r01 = __floats2half2_rn(rx*av.x, ry*av.y);
        half2 r23 = __floats2half2_rn(rz*av.z, rw*av.w);
        unsigned short pa0, pa1, pb0, pb1;
        asm("cvt.rn.satfinite.e4m3x2.f16x2 %0, %1;" : "=h"(pa0) : "r"(*(unsigned*)&l01));
        asm("cvt.rn.satfinite.e4m3x2.f16x2 %0, %1;" : "=h"(pa1) : "r"(*(unsigned*)&l23));
        asm("cvt.rn.satfinite.e4m3x2.f16x2 %0, %1;" : "=h"(pb0) : "r"(*(unsigned*)&r01));
        asm("cvt.rn.satfinite.e4m3x2.f16x2 %0, %1;" : "=h"(pb1) : "r"(*(unsigned*)&r23));
        unsigned ua, ub;
        asm("mov.b32 %0, {%1,%2};" : "=r"(ua) : "h"(pa0), "h"(pa1));
        asm("mov.b32 %0, {%1,%2};" : "=r"(ub) : "h"(pb0), "h"(pb1));
        g_xl8[n * 16 + j] = ua;
        g_xr8[n * 16 + j] = ub;

        // adl = att.(x@W_l): exact fp32 reduce over 16 lanes of this node
        float p = av.x*lx + av.y*ly + av.z*lz + av.w*lw;
        p += __shfl_xor_sync(FULL, p, 8);
        p += __shfl_xor_sync(FULL, p, 4);
        p += __shfl_xor_sync(FULL, p, 2);
        p += __shfl_xor_sync(FULL, p, 1);

        if (j == 0) {
            float w = __expf(0.6f * p);   // dst-side linear term cancels in softmax
            float4* q = (float4*)(g_xww + n * 8);
            q[0] = make_float4(w*xn.x, w*xn.y, w*xn.z, w*xn.w);
            q[1] = make_float4(w, 0.f, 0.f, 0.f);
            float4* a = (float4*)(g_accden + n * 8);
            a[0] = make_float4(0.f, 0.f, 0.f, 0.f);
            a[1] = make_float4(0.f, 0.f, 0.f, 0.f);
        }
    }
}

// -------- kernel 3: edge-parallel attention, e4m3 rows, 4 lanes/edge --------
// lane: sub = lane>>2 selects edge (8/warp), k2 = lane&3 owns ch [16k2,16k2+16)
__global__ void __launch_bounds__(256)
k_edge(const int* __restrict__ ei, const float* __restrict__ att) {
    int tid  = blockIdx.x * blockDim.x + threadIdx.x;
    int lane = threadIdx.x & 31;
    int sub  = lane >> 2;
    int k2   = lane & 3;

    // sign-fold masks for this lane's 16 channels (8 half2 pairs)
    const float4* att4 = (const float4*)att;
    unsigned msk[8];
    #pragma unroll
    for (int i = 0; i < 4; i++) {
        float4 a = att4[4*k2 + i];
        msk[2*i]   = (a.x < 0.f ? 0x8000u : 0u) | (a.y < 0.f ? 0x80000000u : 0u);
        msk[2*i+1] = (a.z < 0.f ? 0x8000u : 0u) | (a.w < 0.f ? 0x80000000u : 0u);
    }

    const uint4* xl4 = (const uint4*)g_xl8;   // row = 4 uint4
    const uint4* xr4 = (const uint4*)g_xr8;

    int warpId = tid >> 5;
    const int NW = (EDGE_BLOCKS * 256) >> 5;
    const int NO = N_EDGES / 8;

    for (int oct = warpId; oct < NO; oct += NW) {
        int e   = oct * 8 + sub;
        int src = ei[e];
        int dst = ei[N_EDGES + e];

        uint4 A = xl4[src * 4 + k2];
        uint4 B = xr4[dst * 4 + k2];

        unsigned s0 = 0u, s1 = 0u;
        #pragma unroll
        for (int q = 0; q < 4; q++) {
            unsigned a = (q == 0) ? A.x : (q == 1) ? A.y : (q == 2) ? A.z : A.w;
            unsigned b = (q == 0) ? B.x : (q == 1) ? B.y : (q == 2) ? B.z : B.w;
            unsigned short alo, ahi, blo, bhi;
            asm("mov.b32 {%0,%1}, %2;" : "=h"(alo), "=h"(ahi) : "r"(a));
            asm("mov.b32 {%0,%1}, %2;" : "=h"(blo), "=h"(bhi) : "r"(b));
            unsigned ha0, ha1, hb0, hb1, h0, h1;
            asm("cvt.rn.f16x2.e4m3x2 %0, %1;" : "=r"(ha0) : "h"(alo));
            asm("cvt.rn.f16x2.e4m3x2 %0, %1;" : "=r"(ha1) : "h"(ahi));
            asm("cvt.rn.f16x2.e4m3x2 %0, %1;" : "=r"(hb0) : "h"(blo));
            asm("cvt.rn.f16x2.e4m3x2 %0, %1;" : "=r"(hb1) : "h"(bhi));
            asm("add.rn.f16x2 %0, %1, %2;" : "=r"(h0) : "r"(ha0), "r"(hb0));
            asm("add.rn.f16x2 %0, %1, %2;" : "=r"(h1) : "r"(ha1), "r"(hb1));
            h0 = (h0 & 0x7FFF7FFFu) ^ msk[2*q];
            h1 = (h1 & 0x7FFF7FFFu) ^ msk[2*q + 1];
            asm("add.rn.f16x2 %0, %1, %2;" : "=r"(s0) : "r"(s0), "r"(h0));
            asm("add.rn.f16x2 %0, %1, %2;" : "=r"(s1) : "r"(s1), "r"(h1));
        }
        unsigned st;
        asm("add.rn.f16x2 %0, %1, %2;" : "=r"(st) : "r"(s0), "r"(s1));
        float2 f = __half22float2(*(half2*)&st);
        float eabs = f.x + f.y;

        eabs += __shfl_xor_sync(FULL, eabs, 2);
        eabs += __shfl_xor_sync(FULL, eabs, 1);

        if (k2 == 0) {
            const float4* q = (const float4*)(g_xww + src * 8);
            float4 xw = q[0];
            float  w  = g_xww[src * 8 + 4];   // same 32B sector as xw
            float t  = __expf(0.4f * eabs);
            float ex = t * w;
            float* accp = g_accden + dst * 8;
            asm volatile("red.global.add.v4.f32 [%0], {%1,%2,%3,%4};"
                         :: "l"(accp), "f"(t*xw.x), "f"(t*xw.y), "f"(t*xw.z), "f"(t*xw.w)
                         : "memory");
            asm volatile("red.global.add.f32 [%0], %1;"   // same sector as acc
                         :: "l"(accp + 4), "f"(ex) : "memory");
        }
    }
}

// -------- kernel 4: node finalize + LN/pool stats, 32 nodes/warp --------
__global__ void __launch_bounds__(256)
k_node(const float* __restrict__ W_l, const float* __restrict__ b_l,
       const float* __restrict__ conv_bias,
       const float* __restrict__ ln_w, const float* __restrict__ lin_w,
       const int* __restrict__ batch) {
    __shared__ float sSum, sSq;
    int tid = threadIdx.x;
    if (tid == 0) { sSum = 0.f; sSq = 0.f; }
    __syncthreads();

    int lane = tid & 31;
    int warpId = (blockIdx.x * blockDim.x + tid) >> 5;
    int n0 = warpId * 32;
    int c = lane;

    float W0a = W_l[c],        W1a = W_l[64 + c],  W2a = W_l[128 + c],  W3a = W_l[192 + c];
    float W0b = W_l[c + 32],   W1b = W_l[96 + c],  W2b = W_l[160 + c],  W3b = W_l[224 + c];
    float bla = b_l[c],        blb = b_l[c + 32];
    float cba = conv_bias[c],  cbb = conv_bias[c + 32];
    float wta = ln_w[c] * lin_w[c];
    float wtb = ln_w[c + 32] * lin_w[c + 32];

    float accS = 0.f, accQ = 0.f, tAcc = 0.f;
    int   cnt = 0, curG = 0;

    if (n0 < N_NODES) {
        int nl = n0 + lane;
        bool okl = nl < N_NODES;
        // per-node data loaded in parallel across lanes (strided 32B slots)
        float4 acc_l = okl ? *(const float4*)(g_accden + nl * 8)
                           : make_float4(0.f, 0.f, 0.f, 0.f);
        float  den_l = okl ? g_accden[nl * 8 + 4] : 0.f;
        int    g_lv  = okl ? batch[nl] : 0;
        float invd_l = den_l > 0.f ? 1.f / den_l : 0.f;

        curG = __shfl_sync(FULL, g_lv, 0);
        int m = min(32, N_NODES - n0);

        for (int i = 0; i < m; i++) {
            float invd = __shfl_sync(FULL, invd_l, i);
            int   g    = __shfl_sync(FULL, g_lv, i);
            float ax   = __shfl_sync(FULL, acc_l.x, i);
            float ay   = __shfl_sync(FULL, acc_l.y, i);
            float az   = __shfl_sync(FULL, acc_l.z, i);
            float aw   = __shfl_sync(FULL, acc_l.w, i);
            float bsel = invd > 0.f ? 1.f : 0.f;

            if (g != curG) {
                float tw = tAcc;
                #pragma unroll
                for (int off = 16; off > 0; off >>= 1)
                    tw += __shfl_xor_sync(FULL, tw, off);
                if (lane == 0) {
                    atomicAdd(&g_S[curG], (double)tw);
                    atomicAdd(&g_cnt[curG], cnt);
                }
                tAcc = 0.f; cnt = 0; curG = g;
            }

            float oa = ax*W0a + ay*W1a + az*W2a + aw*W3a;
            float ob = ax*W0b + ay*W1b + az*W2b + aw*W3b;
            float va = fmaxf(fmaf(oa, invd, fmaf(bsel, bla, cba)), 0.f);
            float vb = fmaxf(fmaf(ob, invd, fmaf(bsel, blb, cbb)), 0.f);

            accS += va + vb;
            accQ += va*va + vb*vb;
            tAcc += va*wta + vb*wtb;
            cnt++;
        }

        float tw = tAcc;
        #pragma unroll
        for (int off = 16; off > 0; off >>= 1)
            tw += __shfl_xor_sync(FULL, tw, off);
        if (lane == 0 && cnt > 0) {
            atomicAdd(&g_S[curG], (double)tw);
            atomicAdd(&g_cnt[curG], cnt);
        }
    }

    #pragma unroll
    for (int off = 16; off > 0; off >>= 1) {
        accS += __shfl_xor_sync(FULL, accS, off);
        accQ += __shfl_xor_sync(FULL, accQ, off);
    }
    if (lane == 0) {
        atomicAdd(&sSum, accS);
        atomicAdd(&sSq,  accQ);
    }
    __syncthreads();
    if (tid == 0) {
        atomicAdd(&g_sum, (double)sSum);
        atomicAdd(&g_sq,  (double)sSq);
    }
}

// -------- kernel 5: final scalar combine + sigmoid --------
__global__ void k_final(float* __restrict__ out) {
    int t = threadIdx.x;
    double Ntot = (double)N_NODES * HID;
    double mu_d  = g_sum / Ntot;
    double var_d = g_sq / Ntot - mu_d * mu_d;
    float mu  = (float)mu_d;
    float inv = rsqrtf((float)var_d + LN_EPS);

    float cnt = fmaxf((float)g_cnt[t], 1.f);
    float y = inv * ((float)g_S[t] / cnt - mu * g_sW) + g_sB;
    out[t] = 1.f / (1.f + __expf(-y));
}

extern "C" void kernel_launch(void* const* d_in, const int* in_sizes, int n_in,
                              void* d_out, int out_size) {
    const float* x         = (const float*)d_in[0];
    const int*   ei        = (const int*)  d_in[1];
    const int*   batch     = (const int*)  d_in[2];
    const float* W_l       = (const float*)d_in[3];
    const float* b_l       = (const float*)d_in[4];
    const float* W_r       = (const float*)d_in[5];
    const float* b_r       = (const float*)d_in[6];
    const float* att       = (const float*)d_in[7];
    const float* conv_bias = (const float*)d_in[8];
    const float* ln_w      = (const float*)d_in[9];
    const float* ln_b      = (const float*)d_in[10];
    const float* lin_w     = (const float*)d_in[11];
    const float* lin_b     = (const float*)d_in[12];
    float* out = (float*)d_out;

    k_const<<<1, 32>>>(ln_w, ln_b, lin_w, lin_b);
    k_prehalf<<<PRE_BLOCKS, 256>>>(x, W_l, W_r, att, b_l, b_r);
    k_edge<<<EDGE_BLOCKS, 256>>>(ei, att);
    k_node<<<NODE_BLOCKS, 256>>>(W_l, b_l, conv_bias, ln_w, lin_w, batch);
    k_final<<<1, N_GRAPHS>>>(out);
}